// round 15
// baseline (speedup 1.0000x reference)
#include <cuda_runtime.h>

#define NB 64
#define TD 2048
#define TE 512
#define G_STEPS 20000
#define LN_GAMMA (-5.0001250041667e-05)   // ln(0.99995)
#define LOG2E 1.4426950408889634
#define GRID 888                          // 148 SMs x 6 blocks
#define CHUNK_SHIFT 3                     // 8 rows per unit
#define CHUNKS_PER_B (TD >> CHUNK_SHIFT)  // 256
#define NCHUNK (NB * CHUNKS_PER_B)        // 16384
#define MAXU 20                           // ceil(NCHUNK/GRID)=19

typedef unsigned long long u64;
typedef unsigned int u32;

__device__ float g_partial[GRID];
__device__ unsigned int g_ticket = 0;     // self-resetting, graph-replay safe

__device__ __forceinline__ float ex2a(float x) {
    float r; asm("ex2.approx.f32 %0, %1;" : "=f"(r) : "f"(x)); return r;
}
__device__ __forceinline__ void cpa16(u32 s, const void* g) {
    asm volatile("cp.async.cg.shared.global [%0], [%1], 16;" :: "r"(s), "l"(g));
}
#define CP_COMMIT() asm volatile("cp.async.commit_group;" ::: "memory")
#define CP_WAIT1()  asm volatile("cp.async.wait_group 1;" ::: "memory")

__device__ __forceinline__ void gal_acc(float& facc, float4 v, float y,
                                        float a0, float a1, float a2, float a3,
                                        float m1, float m2, float m3, float kneg)
{
    const float d0 = a0 - y, d1 = a1 - y, d2 = a2 - y, d3 = a3 - y;
    const float w0 = 1.0f - ex2a(d0 * d0 * kneg);
    const float w1 = 1.0f - ex2a(d1 * d1 * kneg);
    const float w2 = 1.0f - ex2a(d2 * d2 * kneg);
    const float w3 = 1.0f - ex2a(d3 * d3 * kneg);
    facc = fmaf(w0, v.x, facc);
    facc = fmaf(w1, v.y * m1, facc);
    facc = fmaf(w2, v.z * m2, facc);
    facc = fmaf(w3, v.w * m3, facc);
}

__global__ void __launch_bounds__(256, 6) gal_main_kernel(
    const float* __restrict__ A,      // [NB, TD, TE]
    const int*   __restrict__ inL,    // [NB]
    const int*   __restrict__ tgtL,   // [NB]
    const int*   __restrict__ gstep,  // [1]
    float*       __restrict__ out)    // [1]
{
    __shared__ __align__(16) float s_buf[2][8 * TE];    // 32KB double buffer
    __shared__ float s_invL[NB], s_invF[NB], s_scale[NB];
    __shared__ int   s_L[NB], s_F[NB];
    __shared__ int   s_units[MAXU];
    __shared__ int   s_cnt;
    __shared__ float warpsum[8];
    __shared__ int   s_last;

    const int tid = threadIdx.x;
    const int step = *gstep;          // hoisted: overlaps with table setup below

    if (tid < NB) {
        const int L = __ldg(&inL[tid]);
        const int F = __ldg(&tgtL[tid]);
        s_L[tid] = L;
        s_F[tid] = F;
        s_invL[tid]  = 1.0f / (float)L;
        s_invF[tid]  = 1.0f / (float)F;
        s_scale[tid] = 1.0f / ((float)F * (float)NB);
    }
    __syncthreads();

    // build per-block worklist of valid row-units (thread 0, <=19 iters)
    if (tid == 0) {
        int n = 0;
        for (int ch = blockIdx.x; ch < NCHUNK; ch += GRID) {
            const int b  = ch >> 8;
            const int r0 = (ch & (CHUNKS_PER_B - 1)) << CHUNK_SHIFT;
            if (r0 < s_F[b]) s_units[n++] = ch;
        }
        s_cnt = n;
    }
    __syncthreads();

    float partial = 0.0f;
    const int n = s_cnt;

    if (step <= G_STEPS && n > 0) {
        const double gd = exp((double)step * LN_GAMMA);
        const float kneg = (float)(-(0.5 / (gd * gd)) * LOG2E);

        const int half = tid >> 7;            // 0/1: row parity
        const int cidx = (tid & 127) << 2;    // float4 column start
        const float fc0 = (float)cidx;

        const u32 sbase0 = (u32)__cvta_generic_to_shared(&s_buf[0][half * TE + cidx]);
        const u32 sbase1 = (u32)__cvta_generic_to_shared(&s_buf[1][half * TE + cidx]);

        // loader: issue this thread's 4 cp.asyncs for unit j into stage j&1
        auto issue_unit = [&](int j) {
            const int ch = s_units[j];
            const int b  = ch >> 8;
            const int r0 = (ch & (CHUNKS_PER_B - 1)) << CHUNK_SHIFT;
            const int L  = s_L[b];
            if (cidx < L) {
                const int rows = min(8, s_F[b] - r0);
                const float* p = A + ((size_t)b << 20)
                                   + ((size_t)(r0 + half) << 9) + cidx;
                const u32 q = (j & 1) ? sbase1 : sbase0;
                #pragma unroll
                for (int k = 0; k < 4; ++k) {
                    if (half + 2 * k < rows)
                        cpa16(q + (u32)(2 * k * TE) * 4u, p + 2 * k * TE);
                }
            }
        };

        // prologue: always commit 2 groups (empty groups are legal)
        issue_unit(0);
        CP_COMMIT();
        if (n > 1) issue_unit(1);
        CP_COMMIT();

        for (int i = 0; i < n; ++i) {
            CP_WAIT1();                        // group for unit i complete

            const int ch = s_units[i];
            const int b  = ch >> 8;
            const int r0 = (ch & (CHUNKS_PER_B - 1)) << CHUNK_SHIFT;
            const int L  = s_L[b];

            if (cidx < L) {
                const int F = s_F[b];
                const int rows = min(8, F - r0);
                const float invL = s_invL[b];
                const float invF = s_invF[b];
                const float a0 = fc0 * invL;
                const float a1 = (fc0 + 1.0f) * invL;
                const float a2 = (fc0 + 2.0f) * invL;
                const float a3 = (fc0 + 3.0f) * invL;
                const float m1 = (cidx + 1 < L) ? 1.0f : 0.0f;
                const float m2 = (cidx + 2 < L) ? 1.0f : 0.0f;
                const float m3 = (cidx + 3 < L) ? 1.0f : 0.0f;

                const float y0 = (float)(r0 + half) * invF;
                const float ys = 2.0f * invF;

                const float* sp = &s_buf[i & 1][half * TE + cidx];
                float facc = 0.0f;
                if (rows == 8) {
                    const float4 v0 = *(const float4*)(sp);
                    const float4 v1 = *(const float4*)(sp + 1024);
                    const float4 v2 = *(const float4*)(sp + 2048);
                    const float4 v3 = *(const float4*)(sp + 3072);
                    gal_acc(facc, v0, y0,          a0, a1, a2, a3, m1, m2, m3, kneg);
                    gal_acc(facc, v1, y0 + ys,     a0, a1, a2, a3, m1, m2, m3, kneg);
                    gal_acc(facc, v2, y0 + 2.f*ys, a0, a1, a2, a3, m1, m2, m3, kneg);
                    gal_acc(facc, v3, y0 + 3.f*ys, a0, a1, a2, a3, m1, m2, m3, kneg);
                } else {
                    #pragma unroll
                    for (int k = 0; k < 4; ++k) {
                        if (half + 2 * k < rows) {
                            const float4 v = *(const float4*)(sp + k * 1024);
                            gal_acc(facc, v, y0 + (float)k * ys,
                                    a0, a1, a2, a3, m1, m2, m3, kneg);
                        }
                    }
                }
                partial = fmaf(facc, s_scale[b], partial);
            }

            if (i + 2 < n) issue_unit(i + 2);
            CP_COMMIT();                       // always commit: uniform counting
        }
    }

    // block reduction
    #pragma unroll
    for (int o = 16; o > 0; o >>= 1)
        partial += __shfl_down_sync(0xffffffffu, partial, o);
    const int wid = tid >> 5, lid = tid & 31;
    if (lid == 0) warpsum[wid] = partial;
    __syncthreads();
    if (tid == 0) {
        float v = 0.0f;
        #pragma unroll
        for (int w = 0; w < 8; ++w) v += warpsum[w];
        g_partial[blockIdx.x] = v;
        __threadfence();
        const unsigned int t = atomicAdd(&g_ticket, 1u);
        s_last = (t == GRID - 1) ? 1 : 0;
    }
    __syncthreads();

    // last finishing block: fused finalize (replay-safe ticket reset)
    if (s_last) {
        float s = 0.0f;
        for (int i = tid; i < GRID; i += 256)
            s += __ldcg(&g_partial[i]);
        #pragma unroll
        for (int o = 16; o > 0; o >>= 1)
            s += __shfl_down_sync(0xffffffffu, s, o);
        if (lid == 0) warpsum[wid] = s;
        __syncthreads();
        if (tid == 0) {
            float v = 0.0f;
            #pragma unroll
            for (int w = 0; w < 8; ++w) v += warpsum[w];
            out[0] = v;
            g_ticket = 0;
            __threadfence();
        }
    }
}

extern "C" void kernel_launch(void* const* d_in, const int* in_sizes, int n_in,
                              void* d_out, int out_size) {
    const float* A   = (const float*)d_in[0];
    const int* inL   = (const int*)d_in[1];
    const int* tgtL  = (const int*)d_in[2];
    const int* gstep = (const int*)d_in[3];
    float* out       = (float*)d_out;

    gal_main_kernel<<<GRID, 256>>>(A, inL, tgtL, gstep, out);
}

// round 16
// speedup vs baseline: 1.1048x; 1.1048x over previous
#include <cuda_runtime.h>

#define NB 64
#define TD 2048
#define TE 512
#define G_STEPS 20000
#define LN_GAMMA (-5.0001250041667e-05)   // ln(0.99995)
#define LOG2E 1.4426950408889634
#define GRID 888                          // 148 SMs x 6 blocks
#define CHUNK_SHIFT 3                     // 8 rows per unit
#define CHUNKS_PER_B (TD >> CHUNK_SHIFT)  // 256
#define NCHUNK (NB * CHUNKS_PER_B)        // 16384
#define MAXU 20                           // ceil(NCHUNK/GRID)=19

typedef unsigned long long u64;
typedef unsigned int u32;

__device__ float g_partial[GRID];
__device__ unsigned int g_ticket = 0;

__device__ __forceinline__ float ex2a(float x) {
    float r; asm("ex2.approx.f32 %0, %1;" : "=f"(r) : "f"(x)); return r;
}
__device__ __forceinline__ u64 pack2(float lo, float hi) {
    u64 r; asm("mov.b64 %0, {%1, %2};" : "=l"(r) : "f"(lo), "f"(hi)); return r;
}
__device__ __forceinline__ void unpack2(float& lo, float& hi, u64 v) {
    asm("mov.b64 {%0, %1}, %2;" : "=f"(lo), "=f"(hi) : "l"(v));
}
__device__ __forceinline__ u64 add2(u64 a, u64 b) {
    u64 r; asm("add.rn.f32x2 %0, %1, %2;" : "=l"(r) : "l"(a), "l"(b)); return r;
}
__device__ __forceinline__ u64 mul2(u64 a, u64 b) {
    u64 r; asm("mul.rn.f32x2 %0, %1, %2;" : "=l"(r) : "l"(a), "l"(b)); return r;
}
__device__ __forceinline__ u64 fma2(u64 a, u64 b, u64 c) {
    u64 r; asm("fma.rn.f32x2 %0, %1, %2, %3;" : "=l"(r) : "l"(a), "l"(b), "l"(c)); return r;
}
__device__ __forceinline__ void cpa16(u32 s, const void* g) {
    asm volatile("cp.async.cg.shared.global [%0], [%1], 16;" :: "r"(s), "l"(g));
}
#define CP_COMMIT() asm volatile("cp.async.commit_group;" ::: "memory")
#define CP_WAIT1()  asm volatile("cp.async.wait_group 1;" ::: "memory")

// one row of 4 elements, packed: acc += (m - m*exp2(k*d^2)) * v ; advances negy
__device__ __forceinline__ void gal_row(u64& acc, u64& negy, ulonglong2 vv,
                                        u64 a01, u64 a23, u64 kneg2,
                                        u64 m01, u64 m23, u64 nm01, u64 nm23,
                                        u64 negys2)
{
    const u64 d0 = add2(a01, negy);
    const u64 d1 = add2(a23, negy);
    const u64 t0 = mul2(d0, kneg2);
    const u64 t1 = mul2(d1, kneg2);
    const u64 g0 = mul2(t0, d0);
    const u64 g1 = mul2(t1, d1);
    float e0, e1, e2, e3;
    unpack2(e0, e1, g0);
    unpack2(e2, e3, g1);
    const u64 w0 = pack2(ex2a(e0), ex2a(e1));
    const u64 w1 = pack2(ex2a(e2), ex2a(e3));
    const u64 mw0 = fma2(w0, nm01, m01);   // m - m*w
    const u64 mw1 = fma2(w1, nm23, m23);
    acc = fma2(mw0, vv.x, acc);
    acc = fma2(mw1, vv.y, acc);
    negy = add2(negy, negys2);
}

__global__ void __launch_bounds__(256, 6) gal_main_kernel(
    const float* __restrict__ A,      // [NB, TD, TE]
    const int*   __restrict__ inL,    // [NB]
    const int*   __restrict__ tgtL,   // [NB]
    const int*   __restrict__ gstep,  // [1]
    float*       __restrict__ out)    // [1]
{
    __shared__ float s_buf[2][8 * TE];     // 32KB double buffer
    __shared__ float s_invL[NB], s_invF[NB], s_scale[NB];
    __shared__ int   s_L[NB], s_F[NB];
    __shared__ int   s_units[MAXU];
    __shared__ int   s_cnt;
    __shared__ float warpsum[8];
    __shared__ int   s_last;

    const int tid = threadIdx.x;
    if (tid < NB) {
        const int L = inL[tid];
        const int F = tgtL[tid];
        s_L[tid] = L;
        s_F[tid] = F;
        s_invL[tid]  = 1.0f / (float)L;
        s_invF[tid]  = 1.0f / (float)F;
        s_scale[tid] = 1.0f / ((float)F * (float)NB);
    }
    __syncthreads();

    // build per-block worklist of valid row-units (thread 0, <=19 iters)
    if (tid == 0) {
        int n = 0;
        for (int ch = blockIdx.x; ch < NCHUNK; ch += GRID) {
            const int b  = ch >> 8;
            const int r0 = (ch & (CHUNKS_PER_B - 1)) << CHUNK_SHIFT;
            if (r0 < s_F[b]) s_units[n++] = ch;
        }
        s_cnt = n;
    }
    __syncthreads();

    float partial = 0.0f;
    const int step = *gstep;
    const int n = s_cnt;

    if (step <= G_STEPS && n > 0) {
        const double gd = exp((double)step * LN_GAMMA);
        const float kneg = (float)(-(0.5 / (gd * gd)) * LOG2E);
        const u64 kneg2 = pack2(kneg, kneg);

        const int half = tid >> 7;            // 0/1: row parity
        const int cidx = (tid & 127) << 2;    // float4 column start
        const u64 fc01 = pack2((float)cidx,       (float)(cidx + 1));
        const u64 fc23 = pack2((float)(cidx + 2), (float)(cidx + 3));

        // smem slot base for this thread's stage rows (generic->shared u32)
        const u32 sbase0 = (u32)__cvta_generic_to_shared(
                                    &s_buf[0][half * TE + cidx]);
        const u32 sbase1 = (u32)__cvta_generic_to_shared(
                                    &s_buf[1][half * TE + cidx]);

        // ---- loader: issue this thread's 4 cp.asyncs for unit j into stage j&1
        auto issue_unit = [&](int j) {
            const int ch = s_units[j];
            const int b  = ch >> 8;
            const int r0 = (ch & (CHUNKS_PER_B - 1)) << CHUNK_SHIFT;
            const int L  = s_L[b];
            if (cidx < L) {
                const int rows = min(8, s_F[b] - r0);
                const float* p = A + ((size_t)b << 20)
                                   + ((size_t)(r0 + half) << 9) + cidx;
                const u32 q = (j & 1) ? sbase1 : sbase0;
                #pragma unroll
                for (int k = 0; k < 4; ++k) {
                    if (half + 2 * k < rows)
                        cpa16(q + (u32)(2 * k * TE) * 4u, p + 2 * k * TE);
                }
            }
        };

        u64 partial2 = 0ull;

        // prologue: always commit 2 groups (empty groups are legal)
        issue_unit(0);
        CP_COMMIT();
        if (n > 1) issue_unit(1);
        CP_COMMIT();

        for (int i = 0; i < n; ++i) {
            CP_WAIT1();                        // group for unit i complete

            const int ch = s_units[i];
            const int b  = ch >> 8;
            const int r0 = (ch & (CHUNKS_PER_B - 1)) << CHUNK_SHIFT;
            const int L  = s_L[b];

            if (cidx < L) {
                const int F = s_F[b];
                const int rows = min(8, F - r0);
                const float invL = s_invL[b];
                const float invF = s_invF[b];
                const u64 invL2 = pack2(invL, invL);
                const u64 a01 = mul2(fc01, invL2);
                const u64 a23 = mul2(fc23, invL2);
                const float m1 = (cidx + 1 < L) ? 1.0f : 0.0f;
                const float m2 = (cidx + 2 < L) ? 1.0f : 0.0f;
                const float m3 = (cidx + 3 < L) ? 1.0f : 0.0f;
                const u64 m01  = pack2(1.0f, m1);
                const u64 m23  = pack2(m2, m3);
                const u64 nm01 = pack2(-1.0f, -m1);
                const u64 nm23 = pack2(-m2, -m3);

                const float ynf = -(float)(r0 + half) * invF;
                u64 negy = pack2(ynf, ynf);
                const float yst = -2.0f * invF;
                const u64 negys2 = pack2(yst, yst);

                const float* sp = &s_buf[i & 1][half * TE + cidx];
                u64 acc = 0ull;
                if (rows == 8) {
                    const ulonglong2 v0 = *(const ulonglong2*)(sp);
                    const ulonglong2 v1 = *(const ulonglong2*)(sp + 1024);
                    const ulonglong2 v2 = *(const ulonglong2*)(sp + 2048);
                    const ulonglong2 v3 = *(const ulonglong2*)(sp + 3072);
                    gal_row(acc, negy, v0, a01, a23, kneg2, m01, m23, nm01, nm23, negys2);
                    gal_row(acc, negy, v1, a01, a23, kneg2, m01, m23, nm01, nm23, negys2);
                    gal_row(acc, negy, v2, a01, a23, kneg2, m01, m23, nm01, nm23, negys2);
                    gal_row(acc, negy, v3, a01, a23, kneg2, m01, m23, nm01, nm23, negys2);
                } else {
                    #pragma unroll
                    for (int k = 0; k < 4; ++k) {
                        if (half + 2 * k < rows) {
                            const ulonglong2 v = *(const ulonglong2*)(sp + k * 1024);
                            gal_row(acc, negy, v, a01, a23, kneg2,
                                    m01, m23, nm01, nm23, negys2);
                        } else {
                            negy = add2(negy, negys2);
                        }
                    }
                }
                const float sc = s_scale[b];
                partial2 = fma2(acc, pack2(sc, sc), partial2);
            }

            if (i + 2 < n) issue_unit(i + 2);
            CP_COMMIT();                       // always commit: uniform counting
        }

        float plo, phi;
        unpack2(plo, phi, partial2);
        partial = plo + phi;
    }

    // block reduction
    #pragma unroll
    for (int o = 16; o > 0; o >>= 1)
        partial += __shfl_down_sync(0xffffffffu, partial, o);
    const int wid = tid >> 5, lid = tid & 31;
    if (lid == 0) warpsum[wid] = partial;
    __syncthreads();
    if (tid == 0) {
        float v = 0.0f;
        #pragma unroll
        for (int w = 0; w < 8; ++w) v += warpsum[w];
        g_partial[blockIdx.x] = v;
        __threadfence();
        const unsigned int t = atomicAdd(&g_ticket, 1u);
        s_last = (t == GRID - 1) ? 1 : 0;
    }
    __syncthreads();

    // last finishing block: fused finalize
    if (s_last) {
        float s = 0.0f;
        for (int i = tid; i < GRID; i += 256)
            s += __ldcg(&g_partial[i]);
        #pragma unroll
        for (int o = 16; o > 0; o >>= 1)
            s += __shfl_down_sync(0xffffffffu, s, o);
        if (lid == 0) warpsum[wid] = s;
        __syncthreads();
        if (tid == 0) {
            float v = 0.0f;
            #pragma unroll
            for (int w = 0; w < 8; ++w) v += warpsum[w];
            out[0] = v;
            g_ticket = 0;          // reset for next graph replay
            __threadfence();
        }
    }
}

extern "C" void kernel_launch(void* const* d_in, const int* in_sizes, int n_in,
                              void* d_out, int out_size) {
    const float* A   = (const float*)d_in[0];
    const int* inL   = (const int*)d_in[1];
    const int* tgtL  = (const int*)d_in[2];
    const int* gstep = (const int*)d_in[3];
    float* out       = (float*)d_out;

    gal_main_kernel<<<GRID, 256>>>(A, inL, tgtL, gstep, out);
}